// round 8
// baseline (speedup 1.0000x reference)
#include <cuda_runtime.h>
#include <cstdint>
#include <math.h>

typedef unsigned long long u64;

#define BB 2
#define LL 256
#define HH 512
#define NHH 8
#define DHH 64

// ---------------- device scratch ----------------
__device__ float g_qt  [BB*NHH*LL*DHH];   // [b,n,l,d]
__device__ float g_kt  [BB*NHH*LL*DHH];   // [b,n,l,d]
__device__ float g_vt  [BB*NHH*LL*DHH];   // [b,n,l,d]
__device__ float g_w2  [BB*LL*NHH*HH];    // [b,q,n,h]
__device__ float g_ac  [BB*NHH*LL*LL];    // [b,n,q,k]
__device__ float g_attn[BB*NHH*LL*LL];    // [b,n,q,k]
__device__ float g_pre [BB*LL*HH];        // [b,q, n*64+d]

// ---------------- helpers ----------------
__device__ __forceinline__ u64 fma2(u64 a, u64 b, u64 c) {
    u64 d; asm("fma.rn.f32x2 %0, %1, %2, %3;" : "=l"(d) : "l"(a), "l"(b), "l"(c)); return d;
}
__device__ __forceinline__ u64 pack2(float x, float y) {
    u64 r; asm("mov.b64 %0, {%1, %2};" : "=l"(r) : "f"(x), "f"(y)); return r;
}
__device__ __forceinline__ float2 unpack2(u64 v) {
    float2 r; asm("mov.b64 {%0, %1}, %2;" : "=f"(r.x), "=f"(r.y) : "l"(v)); return r;
}

#define CP_ASYNC16(dst, src) asm volatile("cp.async.cg.shared.global [%0], [%1], 16;" :: "r"(dst), "l"(src))
#define CP_COMMIT()          asm volatile("cp.async.commit_group;")
#define CP_WAIT3()           asm volatile("cp.async.wait_group 3;")

// ---------------- shared 64x64 mma inner (32-k step) ----------------
__device__ __forceinline__ void mma32(const float (*As)[68], const float (*Bs)[68],
                                      int ty4, int tx4, u64 acc[2][4]) {
#pragma unroll
    for (int kk = 0; kk < 32; kk++) {
        ulonglong2 a2 = *(const ulonglong2*)&As[kk][ty4];
        float4 bv = *(const float4*)&Bs[kk][tx4];
        u64 b0 = pack2(bv.x, bv.x), b1 = pack2(bv.y, bv.y);
        u64 b2 = pack2(bv.z, bv.z), b3 = pack2(bv.w, bv.w);
        acc[0][0] = fma2(a2.x, b0, acc[0][0]); acc[1][0] = fma2(a2.y, b0, acc[1][0]);
        acc[0][1] = fma2(a2.x, b1, acc[0][1]); acc[1][1] = fma2(a2.y, b1, acc[1][1]);
        acc[0][2] = fma2(a2.x, b2, acc[0][2]); acc[1][2] = fma2(a2.y, b2, acc[1][2]);
        acc[0][3] = fma2(a2.x, b3, acc[0][3]); acc[1][3] = fma2(a2.y, b3, acc[1][3]);
    }
}

#define STS8A(buf, v0, v1) { \
    As[buf][lk+0][lrow]=v0.x; As[buf][lk+1][lrow]=v0.y; As[buf][lk+2][lrow]=v0.z; As[buf][lk+3][lrow]=v0.w; \
    As[buf][lk+4][lrow]=v1.x; As[buf][lk+5][lrow]=v1.y; As[buf][lk+6][lrow]=v1.z; As[buf][lk+7][lrow]=v1.w; }
#define STS8B(buf, v0, v1) { \
    Bs[buf][lk+0][lrow]=v0.x; Bs[buf][lk+1][lrow]=v0.y; Bs[buf][lk+2][lrow]=v0.z; Bs[buf][lk+3][lrow]=v0.w; \
    Bs[buf][lk+4][lrow]=v1.x; Bs[buf][lk+5][lrow]=v1.y; Bs[buf][lk+6][lrow]=v1.z; Bs[buf][lk+7][lrow]=v1.w; }

// ---------------- QKV projection NT GEMM, grid (8,8,3) ----------------
__global__ __launch_bounds__(256, 2) void qkv_kernel(
    const float* __restrict__ query, const float* __restrict__ key, const float* __restrict__ value,
    const float* __restrict__ Wq, const float* __restrict__ bq,
    const float* __restrict__ Wk, const float* __restrict__ bk,
    const float* __restrict__ Wv, const float* __restrict__ bv)
{
    int z = blockIdx.z;
    const float* X    = (z == 0) ? query : (z == 1) ? key : value;
    const float* W    = (z == 0) ? Wq    : (z == 1) ? Wk  : Wv;
    const float* bias = (z == 0) ? bq    : (z == 1) ? bk  : bv;

    __shared__ __align__(16) float As[2][32][68];
    __shared__ __align__(16) float Bs[2][32][68];

    int tid = threadIdx.x;
    int m0 = blockIdx.y * 64, n0 = blockIdx.x * 64;
    int lrow = tid >> 2, lk = (tid & 3) * 8;
    int ty4 = (tid >> 4) * 4, tx4 = (tid & 15) * 4;

    const float* Arow = X + (m0 + lrow) * HH + lk;
    const float* Brow = W + (n0 + lrow) * HH + lk;
    float4 ra0 = *(const float4*)(Arow),     ra1 = *(const float4*)(Arow + 4);
    float4 rb0 = *(const float4*)(Brow),     rb1 = *(const float4*)(Brow + 4);

    u64 acc[2][4];
#pragma unroll
    for (int p = 0; p < 2; p++)
#pragma unroll
        for (int j = 0; j < 4; j++) acc[p][j] = 0ull;

#pragma unroll 1
    for (int s = 0; s < 16; s++) {
        int buf = s & 1;
        STS8A(buf, ra0, ra1); STS8B(buf, rb0, rb1);
        __syncthreads();
        if (s + 1 < 16) {
            ra0 = *(const float4*)(Arow + (s+1)*32);  ra1 = *(const float4*)(Arow + (s+1)*32 + 4);
            rb0 = *(const float4*)(Brow + (s+1)*32);  rb1 = *(const float4*)(Brow + (s+1)*32 + 4);
        }
        mma32(As[buf], Bs[buf], ty4, tx4, acc);
        __syncthreads();
    }

#pragma unroll
    for (int p = 0; p < 2; p++)
#pragma unroll
        for (int j = 0; j < 4; j++) {
            float2 t = unpack2(acc[p][j]);
            int c = n0 + tx4 + j;
            float bb = bias[c];
            int n_ = c >> 6, d_ = c & 63;
#pragma unroll
            for (int e = 0; e < 2; e++) {
                int m = m0 + ty4 + 2*p + e;
                int b_ = m >> 8, l_ = m & 255;
                size_t idx = ((size_t)(b_*NHH + n_)*LL + l_)*DHH + d_;
                float v = ((e == 0) ? t.x : t.y) + bb;
                if (z == 0)      g_qt[idx] = v;
                else if (z == 1) g_kt[idx] = v;
                else             g_vt[idx] = v;
            }
        }
}

// ---------------- W2 GEMM (double-buffered): g_w2[b,q,n,h], grid (8,8,8) ----------------
__global__ __launch_bounds__(256, 2) void w2_kernel(const float* __restrict__ Wr,
                                                    const float* __restrict__ v_bias)
{
    int n = blockIdx.z;
    int m0 = blockIdx.y * 64, h0 = blockIdx.x * 64;

    __shared__ __align__(16) float As[2][32][68];
    __shared__ __align__(16) float Bs[2][32][68];

    int tid = threadIdx.x;
    int lrow = tid >> 2, lk = (tid & 3) * 8;
    int brow = tid >> 3, bcol = (tid & 7) * 8;
    int ty4 = (tid >> 4) * 4, tx4 = (tid & 15) * 4;

    int m = m0 + lrow; int b_ = m >> 8, q_ = m & 255;
    const float* Arow = g_qt + ((size_t)(b_*NHH + n)*LL + q_)*DHH + lk;
    const float* Vrow = v_bias + n*DHH + lk;
    const float* Brow = Wr + (size_t)(n*DHH + brow)*HH + h0 + bcol;

    float4 ra0 = *(const float4*)(Arow),  ra1 = *(const float4*)(Arow + 4);
    float4 u0  = *(const float4*)(Vrow),  u1  = *(const float4*)(Vrow + 4);
    ra0.x += u0.x; ra0.y += u0.y; ra0.z += u0.z; ra0.w += u0.w;
    ra1.x += u1.x; ra1.y += u1.y; ra1.z += u1.z; ra1.w += u1.w;
    float4 rb0 = *(const float4*)(Brow),  rb1 = *(const float4*)(Brow + 4);

    u64 acc[2][4];
#pragma unroll
    for (int p = 0; p < 2; p++)
#pragma unroll
        for (int j = 0; j < 4; j++) acc[p][j] = 0ull;

#pragma unroll 1
    for (int s = 0; s < 2; s++) {
        int buf = s & 1;
        STS8A(buf, ra0, ra1);
        *(float4*)&Bs[buf][brow][bcol]     = rb0;
        *(float4*)&Bs[buf][brow][bcol + 4] = rb1;
        __syncthreads();
        if (s == 0) {
            ra0 = *(const float4*)(Arow + 32); ra1 = *(const float4*)(Arow + 36);
            float4 w0 = *(const float4*)(Vrow + 32), w1 = *(const float4*)(Vrow + 36);
            ra0.x += w0.x; ra0.y += w0.y; ra0.z += w0.z; ra0.w += w0.w;
            ra1.x += w1.x; ra1.y += w1.y; ra1.z += w1.z; ra1.w += w1.w;
            rb0 = *(const float4*)(Brow + 32*HH); rb1 = *(const float4*)(Brow + 32*HH + 4);
        }
        mma32(As[buf], Bs[buf], ty4, tx4, acc);
        __syncthreads();
    }

#pragma unroll
    for (int p = 0; p < 2; p++)
#pragma unroll
        for (int j = 0; j < 4; j++) {
            float2 t = unpack2(acc[p][j]);
            int h = h0 + tx4 + j;
            int mm = m0 + ty4 + 2*p;
            int bb_ = mm >> 8, qq_ = mm & 255;
            g_w2[((size_t)(bb_*LL + qq_)*NHH + n)*HH + h] = t.x;
            int mm2 = mm + 1;
            int bb2 = mm2 >> 8, qq2 = mm2 & 255;
            g_w2[((size_t)(bb2*LL + qq2)*NHH + n)*HH + h] = t.y;
        }
}

// ---------------- A_C GEMM: g_ac[bn,q,k] = (qt+u) @ kt^T, grid (4,4,16) ----------------
__global__ __launch_bounds__(256, 2) void ac_kernel(const float* __restrict__ u_bias)
{
    int bn = blockIdx.z;
    int q0 = blockIdx.y * 64, k0 = blockIdx.x * 64;
    int n = bn & 7;

    __shared__ __align__(16) float As[2][32][68];
    __shared__ __align__(16) float Bs[2][32][68];

    int tid = threadIdx.x;
    int lrow = tid >> 2, lk = (tid & 3) * 8;
    int ty4 = (tid >> 4) * 4, tx4 = (tid & 15) * 4;

    const float* Arow = g_qt + ((size_t)bn*LL + q0 + lrow)*DHH + lk;
    const float* Brow = g_kt + ((size_t)bn*LL + k0 + lrow)*DHH + lk;
    const float* Urow = u_bias + n*DHH + lk;

    float4 ra0 = *(const float4*)(Arow),  ra1 = *(const float4*)(Arow + 4);
    float4 u0  = *(const float4*)(Urow),  u1  = *(const float4*)(Urow + 4);
    ra0.x += u0.x; ra0.y += u0.y; ra0.z += u0.z; ra0.w += u0.w;
    ra1.x += u1.x; ra1.y += u1.y; ra1.z += u1.z; ra1.w += u1.w;
    float4 rb0 = *(const float4*)(Brow),  rb1 = *(const float4*)(Brow + 4);

    u64 acc[2][4];
#pragma unroll
    for (int p = 0; p < 2; p++)
#pragma unroll
        for (int j = 0; j < 4; j++) acc[p][j] = 0ull;

#pragma unroll 1
    for (int s = 0; s < 2; s++) {
        int buf = s & 1;
        STS8A(buf, ra0, ra1); STS8B(buf, rb0, rb1);
        __syncthreads();
        if (s == 0) {
            ra0 = *(const float4*)(Arow + 32); ra1 = *(const float4*)(Arow + 36);
            float4 w0 = *(const float4*)(Urow + 32), w1 = *(const float4*)(Urow + 36);
            ra0.x += w0.x; ra0.y += w0.y; ra0.z += w0.z; ra0.w += w0.w;
            ra1.x += w1.x; ra1.y += w1.y; ra1.z += w1.z; ra1.w += w1.w;
            rb0 = *(const float4*)(Brow + 32); rb1 = *(const float4*)(Brow + 36);
        }
        mma32(As[buf], Bs[buf], ty4, tx4, acc);
        __syncthreads();
    }

#pragma unroll
    for (int p = 0; p < 2; p++) {
        float2 t0 = unpack2(acc[p][0]), t1 = unpack2(acc[p][1]);
        float2 t2 = unpack2(acc[p][2]), t3 = unpack2(acc[p][3]);
        int q = q0 + ty4 + 2*p;
        *(float4*)&g_ac[((size_t)bn*LL + q)  *LL + k0 + tx4] = make_float4(t0.x, t1.x, t2.x, t3.x);
        *(float4*)&g_ac[((size_t)bn*LL + q+1)*LL + k0 + tx4] = make_float4(t0.y, t1.y, t2.y, t3.y);
    }
}

// ---------------- B_D + softmax: 256 thr, w2 in SMEM, 2 CTAs/SM, grid (256,2) ----------------
// dyn smem layout: [w2s: 8*512 floats = 16KB][ring: 8 warps * 4 slots * 512 floats = 64KB]
__global__ __launch_bounds__(256, 2) void bd_kernel(
    const float* __restrict__ rel,
    const int* __restrict__ seq_len, const int* __restrict__ lex_num)
{
    extern __shared__ __align__(16) float dyn[];
    float* w2s  = dyn;              // [n*512 + h]
    float* ring = dyn + NHH * HH;
    __shared__ __align__(16) float ss[NHH * 260];   // scores, pitch 260

    int q = blockIdx.x, b = blockIdx.y;
    int tid = threadIdx.x, w = tid >> 5, lane = tid & 31;

    // load w2 into smem, coalesced: 4096 floats = 1024 float4
    {
        const float4* w2g = (const float4*)(g_w2 + (size_t)(b*LL + q)*NHH*HH);
        float4* w2d = (float4*)w2s;
#pragma unroll
        for (int i = 0; i < 4; i++)
            w2d[tid + i*256] = w2g[tid + i*256];
    }

    // preload A_C: warp w owns head w
    {
        const float* acp = g_ac + ((size_t)(b*NHH + w)*LL + q)*LL;
        *(float4*)&ss[w*260 + lane*8]     = *(const float4*)&acp[lane*8];
        *(float4*)&ss[w*260 + lane*8 + 4] = *(const float4*)&acp[lane*8 + 4];
    }

    const float* relrow = rel + (((size_t)(b*LL + q))*LL + w*32)*HH + lane*4;
    float* myring = ring + w*4*HH;
    uint32_t rbase = (uint32_t)__cvta_generic_to_shared(myring) + lane*16;

#define ISSUE_ROW(row, slot) { const float* s_ = relrow + (size_t)(row)*HH; uint32_t d_ = rbase + (slot)*2048; \
    CP_ASYNC16(d_,      s_);       CP_ASYNC16(d_+512,  s_+128); \
    CP_ASYNC16(d_+1024, s_+256);   CP_ASYNC16(d_+1536, s_+384); }

    ISSUE_ROW(0, 0); CP_COMMIT();
    ISSUE_ROW(1, 1); CP_COMMIT();
    ISSUE_ROW(2, 2); CP_COMMIT();
    __syncthreads();   // w2s + A_C preload visible

#pragma unroll 1
    for (int r = 0; r < 32; r++) {
        if (r + 3 < 32) { ISSUE_ROW(r+3, (r+3)&3); }
        CP_COMMIT();
        CP_WAIT3();
        const float* slot = myring + (r & 3)*HH;
        // rel row slice for this lane
        ulonglong2 rv0 = *(const ulonglong2*)&slot[0*128 + lane*4];
        ulonglong2 rv1 = *(const ulonglong2*)&slot[1*128 + lane*4];
        ulonglong2 rv2 = *(const ulonglong2*)&slot[2*128 + lane*4];
        ulonglong2 rv3 = *(const ulonglong2*)&slot[3*128 + lane*4];
        u64 p[8];
#pragma unroll
        for (int n = 0; n < 8; n++) {
            const float* wn = w2s + n*HH + lane*4;
            ulonglong2 w0 = *(const ulonglong2*)(wn);
            ulonglong2 w1 = *(const ulonglong2*)(wn + 128);
            ulonglong2 w2v = *(const ulonglong2*)(wn + 256);
            ulonglong2 w3 = *(const ulonglong2*)(wn + 384);
            u64 acc = fma2(w0.x, rv0.x, 0ull);
            acc = fma2(w0.y, rv0.y, acc);
            acc = fma2(w1.x, rv1.x, acc);
            acc = fma2(w1.y, rv1.y, acc);
            acc = fma2(w2v.x, rv2.x, acc);
            acc = fma2(w2v.y, rv2.y, acc);
            acc = fma2(w3.x, rv3.x, acc);
            acc = fma2(w3.y, rv3.y, acc);
            p[n] = acc;
        }
        // multi-value butterfly: 9 SHFLs, head n lands on lanes 4n..4n+3
        bool h16 = (lane & 16) != 0;
        float a[4];
#pragma unroll
        for (int i = 0; i < 4; i++) {
            float2 tl = unpack2(p[i]), th = unpack2(p[i+4]);
            float sl = tl.x + tl.y, sh = th.x + th.y;
            float keep = h16 ? sh : sl;
            float send = h16 ? sl : sh;
            a[i] = keep + __shfl_xor_sync(0xffffffffu, send, 16);
        }
        bool h8 = (lane & 8) != 0;
        float c[2];
#pragma unroll
        for (int i = 0; i < 2; i++) {
            float keep = h8 ? a[i+2] : a[i];
            float send = h8 ? a[i]   : a[i+2];
            c[i] = keep + __shfl_xor_sync(0xffffffffu, send, 8);
        }
        bool h4 = (lane & 4) != 0;
        float keep = h4 ? c[1] : c[0];
        float send = h4 ? c[0] : c[1];
        float e = keep + __shfl_xor_sync(0xffffffffu, send, 4);
        e += __shfl_xor_sync(0xffffffffu, e, 2);
        e += __shfl_xor_sync(0xffffffffu, e, 1);
        if ((lane & 3) == 0)
            ss[(lane >> 2)*260 + w*32 + r] += e;
    }
    __syncthreads();

    // softmax head w + write attn
    int total = seq_len[b] + lex_num[b];
    {
        float v[8];
        float4 s0 = *(const float4*)&ss[w*260 + lane*8];
        float4 s1 = *(const float4*)&ss[w*260 + lane*8 + 4];
        v[0]=s0.x; v[1]=s0.y; v[2]=s0.z; v[3]=s0.w;
        v[4]=s1.x; v[5]=s1.y; v[6]=s1.z; v[7]=s1.w;
#pragma unroll
        for (int t = 0; t < 8; t++) {
            int kidx = lane*8 + t;
            v[t] = (kidx < total) ? v[t] * 0.125f : -1e15f;
        }
        float mx = v[0];
#pragma unroll
        for (int t = 1; t < 8; t++) mx = fmaxf(mx, v[t]);
#pragma unroll
        for (int sft = 16; sft > 0; sft >>= 1) mx = fmaxf(mx, __shfl_xor_sync(0xffffffffu, mx, sft));
        float sum = 0.f;
#pragma unroll
        for (int t = 0; t < 8; t++) { v[t] = expf(v[t] - mx); sum += v[t]; }
#pragma unroll
        for (int sft = 16; sft > 0; sft >>= 1) sum += __shfl_xor_sync(0xffffffffu, sum, sft);
        float inv = 1.0f / sum;
#pragma unroll
        for (int t = 0; t < 8; t++) v[t] *= inv;
        float* op = g_attn + ((size_t)(b*NHH + w)*LL + q)*LL + lane*8;
        *(float4*)(op)     = make_float4(v[0], v[1], v[2], v[3]);
        *(float4*)(op + 4) = make_float4(v[4], v[5], v[6], v[7]);
    }
}

// ---------------- AV GEMM (NN): g_pre = attn @ v, grid (4,16) ----------------
__global__ __launch_bounds__(256, 2) void av_kernel()
{
    int q0 = blockIdx.x * 64, bn = blockIdx.y;
    int b = bn >> 3, n = bn & 7;

    __shared__ __align__(16) float As[2][32][68];
    __shared__ __align__(16) float Bs[2][32][68];

    int tid = threadIdx.x;
    int lrow = tid >> 2, lk = (tid & 3) * 8;
    int brow = tid >> 3, bcol = (tid & 7) * 8;
    int ty4 = (tid >> 4) * 4, tx4 = (tid & 15) * 4;

    const float* Arow = g_attn + ((size_t)bn*LL + q0 + lrow)*LL + lk;
    const float* Brow = g_vt   + (size_t)bn*LL*DHH + brow*DHH + bcol;

    float4 ra0 = *(const float4*)(Arow),  ra1 = *(const float4*)(Arow + 4);
    float4 rb0 = *(const float4*)(Brow),  rb1 = *(const float4*)(Brow + 4);

    u64 acc[2][4];
#pragma unroll
    for (int p = 0; p < 2; p++)
#pragma unroll
        for (int j = 0; j < 4; j++) acc[p][j] = 0ull;

#pragma unroll 1
    for (int s = 0; s < 8; s++) {
        int buf = s & 1;
        STS8A(buf, ra0, ra1);
        *(float4*)&Bs[buf][brow][bcol]     = rb0;
        *(float4*)&Bs[buf][brow][bcol + 4] = rb1;
        __syncthreads();
        if (s + 1 < 8) {
            ra0 = *(const float4*)(Arow + (s+1)*32);            ra1 = *(const float4*)(Arow + (s+1)*32 + 4);
            rb0 = *(const float4*)(Brow + (s+1)*32*DHH);        rb1 = *(const float4*)(Brow + (s+1)*32*DHH + 4);
        }
        mma32(As[buf], Bs[buf], ty4, tx4, acc);
        __syncthreads();
    }

#pragma unroll
    for (int p = 0; p < 2; p++)
#pragma unroll
        for (int j = 0; j < 4; j++) {
            float2 t = unpack2(acc[p][j]);
            int d = tx4 + j;
            int q = q0 + ty4 + 2*p;
            g_pre[((size_t)(b*LL + q))    *HH + n*DHH + d] = t.x;
            g_pre[((size_t)(b*LL + q + 1))*HH + n*DHH + d] = t.y;
        }
}

// ---------------- final NT GEMM: out = g_pre @ Wf^T + bf, grid (8,8) ----------------
__global__ __launch_bounds__(256, 2) void wf_kernel(const float* __restrict__ Wf,
                                                    const float* __restrict__ bf,
                                                    float* __restrict__ out)
{
    __shared__ __align__(16) float As[2][32][68];
    __shared__ __align__(16) float Bs[2][32][68];

    int tid = threadIdx.x;
    int m0 = blockIdx.y * 64, n0 = blockIdx.x * 64;
    int lrow = tid >> 2, lk = (tid & 3) * 8;
    int ty4 = (tid >> 4) * 4, tx4 = (tid & 15) * 4;

    const float* Arow = g_pre + (m0 + lrow)*HH + lk;
    const float* Brow = Wf    + (n0 + lrow)*HH + lk;
    float4 ra0 = *(const float4*)(Arow),  ra1 = *(const float4*)(Arow + 4);
    float4 rb0 = *(const float4*)(Brow),  rb1 = *(const float4*)(Brow + 4);

    u64 acc[2][4];
#pragma unroll
    for (int p = 0; p < 2; p++)
#pragma unroll
        for (int j = 0; j < 4; j++) acc[p][j] = 0ull;

#pragma unroll 1
    for (int s = 0; s < 16; s++) {
        int buf = s & 1;
        STS8A(buf, ra0, ra1); STS8B(buf, rb0, rb1);
        __syncthreads();
        if (s + 1 < 16) {
            ra0 = *(const float4*)(Arow + (s+1)*32);  ra1 = *(const float4*)(Arow + (s+1)*32 + 4);
            rb0 = *(const float4*)(Brow + (s+1)*32);  rb1 = *(const float4*)(Brow + (s+1)*32 + 4);
        }
        mma32(As[buf], Bs[buf], ty4, tx4, acc);
        __syncthreads();
    }

#pragma unroll
    for (int p = 0; p < 2; p++)
#pragma unroll
        for (int j = 0; j < 4; j++) {
            float2 t = unpack2(acc[p][j]);
            int c = n0 + tx4 + j;
            float bb = bf[c];
            int m = m0 + ty4 + 2*p;
            out[(size_t)m*HH + c]     = t.x + bb;
            out[(size_t)(m+1)*HH + c] = t.y + bb;
        }
}

// ---------------- launch ----------------
extern "C" void kernel_launch(void* const* d_in, const int* in_sizes, int n_in,
                              void* d_out, int out_size) {
    (void)in_sizes; (void)n_in; (void)out_size;
    const float* key     = (const float*)d_in[0];
    const float* query   = (const float*)d_in[1];
    const float* value   = (const float*)d_in[2];
    const float* rel     = (const float*)d_in[3];
    const float* Wk      = (const float*)d_in[4];
    const float* bk      = (const float*)d_in[5];
    const float* Wq      = (const float*)d_in[6];
    const float* bq      = (const float*)d_in[7];
    const float* Wv      = (const float*)d_in[8];
    const float* bv      = (const float*)d_in[9];
    const float* Wr      = (const float*)d_in[10];
    // d_in[11] = br: constant per score row -> cancels in softmax
    const float* u_bias  = (const float*)d_in[12];
    const float* v_bias  = (const float*)d_in[13];
    const float* Wf      = (const float*)d_in[14];
    const float* bf      = (const float*)d_in[15];
    const int*   seq_len = (const int*)d_in[16];
    const int*   lex_num = (const int*)d_in[17];
    float* out = (float*)d_out;

    static int bd_smem_set = 0;
    if (!bd_smem_set) {
        cudaFuncSetAttribute(bd_kernel, cudaFuncAttributeMaxDynamicSharedMemorySize, 81920);
        bd_smem_set = 1;
    }

    qkv_kernel<<<dim3(8, 8, 3), 256>>>(query, key, value, Wq, bq, Wk, bk, Wv, bv);
    w2_kernel<<<dim3(8, 8, NHH), 256>>>(Wr, v_bias);
    ac_kernel<<<dim3(4, 4, 16), 256>>>(u_bias);
    bd_kernel<<<dim3(LL, BB), 256, 81920>>>(rel, seq_len, lex_num);
    av_kernel<<<dim3(4, 16), 256>>>();
    wf_kernel<<<dim3(8, 8), 256>>>(Wf, bf, out);
}

// round 9
// speedup vs baseline: 1.2527x; 1.2527x over previous
#include <cuda_runtime.h>
#include <cstdint>
#include <math.h>

typedef unsigned long long u64;

#define BB 2
#define LL 256
#define HH 512
#define NHH 8
#define DHH 64

// ---------------- device scratch ----------------
__device__ float g_qt  [BB*NHH*LL*DHH];   // [b,n,l,d]
__device__ float g_kt  [BB*NHH*LL*DHH];   // [b,n,l,d]
__device__ float g_vt  [BB*NHH*LL*DHH];   // [b,n,l,d]
__device__ float g_w2  [BB*LL*NHH*HH];    // [b,q,n,h]
__device__ float g_ac  [BB*NHH*LL*LL];    // [b,n,q,k]
__device__ float g_attn[BB*NHH*LL*LL];    // [b,n,q,k]
__device__ float g_pre [BB*LL*HH];        // [b,q, n*64+d]

// ---------------- helpers ----------------
__device__ __forceinline__ u64 fma2(u64 a, u64 b, u64 c) {
    u64 d; asm("fma.rn.f32x2 %0, %1, %2, %3;" : "=l"(d) : "l"(a), "l"(b), "l"(c)); return d;
}
__device__ __forceinline__ u64 pack2(float x, float y) {
    u64 r; asm("mov.b64 %0, {%1, %2};" : "=l"(r) : "f"(x), "f"(y)); return r;
}
__device__ __forceinline__ float2 unpack2(u64 v) {
    float2 r; asm("mov.b64 {%0, %1}, %2;" : "=f"(r.x), "=f"(r.y) : "l"(v)); return r;
}

#define CP_ASYNC16(dst, src) asm volatile("cp.async.cg.shared.global [%0], [%1], 16;" :: "r"(dst), "l"(src))
#define CP_COMMIT()          asm volatile("cp.async.commit_group;")
#define CP_WAIT2()           asm volatile("cp.async.wait_group 2;")

// ---------------- shared 64x64 mma inner (32-k step) ----------------
__device__ __forceinline__ void mma32(const float (*As)[68], const float (*Bs)[68],
                                      int ty4, int tx4, u64 acc[2][4]) {
#pragma unroll
    for (int kk = 0; kk < 32; kk++) {
        ulonglong2 a2 = *(const ulonglong2*)&As[kk][ty4];
        float4 bv = *(const float4*)&Bs[kk][tx4];
        u64 b0 = pack2(bv.x, bv.x), b1 = pack2(bv.y, bv.y);
        u64 b2 = pack2(bv.z, bv.z), b3 = pack2(bv.w, bv.w);
        acc[0][0] = fma2(a2.x, b0, acc[0][0]); acc[1][0] = fma2(a2.y, b0, acc[1][0]);
        acc[0][1] = fma2(a2.x, b1, acc[0][1]); acc[1][1] = fma2(a2.y, b1, acc[1][1]);
        acc[0][2] = fma2(a2.x, b2, acc[0][2]); acc[1][2] = fma2(a2.y, b2, acc[1][2]);
        acc[0][3] = fma2(a2.x, b3, acc[0][3]); acc[1][3] = fma2(a2.y, b3, acc[1][3]);
    }
}

#define STS8A(buf, v0, v1) { \
    As[buf][lk+0][lrow]=v0.x; As[buf][lk+1][lrow]=v0.y; As[buf][lk+2][lrow]=v0.z; As[buf][lk+3][lrow]=v0.w; \
    As[buf][lk+4][lrow]=v1.x; As[buf][lk+5][lrow]=v1.y; As[buf][lk+6][lrow]=v1.z; As[buf][lk+7][lrow]=v1.w; }
#define STS8B(buf, v0, v1) { \
    Bs[buf][lk+0][lrow]=v0.x; Bs[buf][lk+1][lrow]=v0.y; Bs[buf][lk+2][lrow]=v0.z; Bs[buf][lk+3][lrow]=v0.w; \
    Bs[buf][lk+4][lrow]=v1.x; Bs[buf][lk+5][lrow]=v1.y; Bs[buf][lk+6][lrow]=v1.z; Bs[buf][lk+7][lrow]=v1.w; }

// ---------------- QKV projection NT GEMM, grid (8,8,3) ----------------
__global__ __launch_bounds__(256, 2) void qkv_kernel(
    const float* __restrict__ query, const float* __restrict__ key, const float* __restrict__ value,
    const float* __restrict__ Wq, const float* __restrict__ bq,
    const float* __restrict__ Wk, const float* __restrict__ bk,
    const float* __restrict__ Wv, const float* __restrict__ bv)
{
    int z = blockIdx.z;
    const float* X    = (z == 0) ? query : (z == 1) ? key : value;
    const float* W    = (z == 0) ? Wq    : (z == 1) ? Wk  : Wv;
    const float* bias = (z == 0) ? bq    : (z == 1) ? bk  : bv;

    __shared__ __align__(16) float As[2][32][68];
    __shared__ __align__(16) float Bs[2][32][68];

    int tid = threadIdx.x;
    int m0 = blockIdx.y * 64, n0 = blockIdx.x * 64;
    int lrow = tid >> 2, lk = (tid & 3) * 8;
    int ty4 = (tid >> 4) * 4, tx4 = (tid & 15) * 4;

    const float* Arow = X + (m0 + lrow) * HH + lk;
    const float* Brow = W + (n0 + lrow) * HH + lk;
    float4 ra0 = *(const float4*)(Arow),     ra1 = *(const float4*)(Arow + 4);
    float4 rb0 = *(const float4*)(Brow),     rb1 = *(const float4*)(Brow + 4);

    u64 acc[2][4];
#pragma unroll
    for (int p = 0; p < 2; p++)
#pragma unroll
        for (int j = 0; j < 4; j++) acc[p][j] = 0ull;

#pragma unroll 1
    for (int s = 0; s < 16; s++) {
        int buf = s & 1;
        STS8A(buf, ra0, ra1); STS8B(buf, rb0, rb1);
        __syncthreads();
        if (s + 1 < 16) {
            ra0 = *(const float4*)(Arow + (s+1)*32);  ra1 = *(const float4*)(Arow + (s+1)*32 + 4);
            rb0 = *(const float4*)(Brow + (s+1)*32);  rb1 = *(const float4*)(Brow + (s+1)*32 + 4);
        }
        mma32(As[buf], Bs[buf], ty4, tx4, acc);
    }

#pragma unroll
    for (int p = 0; p < 2; p++)
#pragma unroll
        for (int j = 0; j < 4; j++) {
            float2 t = unpack2(acc[p][j]);
            int c = n0 + tx4 + j;
            float bb = bias[c];
            int n_ = c >> 6, d_ = c & 63;
#pragma unroll
            for (int e = 0; e < 2; e++) {
                int m = m0 + ty4 + 2*p + e;
                int b_ = m >> 8, l_ = m & 255;
                size_t idx = ((size_t)(b_*NHH + n_)*LL + l_)*DHH + d_;
                float v = ((e == 0) ? t.x : t.y) + bb;
                if (z == 0)      g_qt[idx] = v;
                else if (z == 1) g_kt[idx] = v;
                else             g_vt[idx] = v;
            }
        }
}

// ---------------- W2 GEMM (double-buffered): g_w2[b,q,n,h], grid (8,8,8) ----------------
__global__ __launch_bounds__(256, 2) void w2_kernel(const float* __restrict__ Wr,
                                                    const float* __restrict__ v_bias)
{
    int n = blockIdx.z;
    int m0 = blockIdx.y * 64, h0 = blockIdx.x * 64;

    __shared__ __align__(16) float As[2][32][68];
    __shared__ __align__(16) float Bs[2][32][68];

    int tid = threadIdx.x;
    int lrow = tid >> 2, lk = (tid & 3) * 8;
    int brow = tid >> 3, bcol = (tid & 7) * 8;
    int ty4 = (tid >> 4) * 4, tx4 = (tid & 15) * 4;

    int m = m0 + lrow; int b_ = m >> 8, q_ = m & 255;
    const float* Arow = g_qt + ((size_t)(b_*NHH + n)*LL + q_)*DHH + lk;
    const float* Vrow = v_bias + n*DHH + lk;
    const float* Brow = Wr + (size_t)(n*DHH + brow)*HH + h0 + bcol;

    float4 ra0 = *(const float4*)(Arow),  ra1 = *(const float4*)(Arow + 4);
    float4 u0  = *(const float4*)(Vrow),  u1  = *(const float4*)(Vrow + 4);
    ra0.x += u0.x; ra0.y += u0.y; ra0.z += u0.z; ra0.w += u0.w;
    ra1.x += u1.x; ra1.y += u1.y; ra1.z += u1.z; ra1.w += u1.w;
    float4 rb0 = *(const float4*)(Brow),  rb1 = *(const float4*)(Brow + 4);

    u64 acc[2][4];
#pragma unroll
    for (int p = 0; p < 2; p++)
#pragma unroll
        for (int j = 0; j < 4; j++) acc[p][j] = 0ull;

#pragma unroll 1
    for (int s = 0; s < 2; s++) {
        int buf = s & 1;
        STS8A(buf, ra0, ra1);
        *(float4*)&Bs[buf][brow][bcol]     = rb0;
        *(float4*)&Bs[buf][brow][bcol + 4] = rb1;
        __syncthreads();
        if (s == 0) {
            ra0 = *(const float4*)(Arow + 32); ra1 = *(const float4*)(Arow + 36);
            float4 w0 = *(const float4*)(Vrow + 32), w1 = *(const float4*)(Vrow + 36);
            ra0.x += w0.x; ra0.y += w0.y; ra0.z += w0.z; ra0.w += w0.w;
            ra1.x += w1.x; ra1.y += w1.y; ra1.z += w1.z; ra1.w += w1.w;
            rb0 = *(const float4*)(Brow + 32*HH); rb1 = *(const float4*)(Brow + 32*HH + 4);
        }
        mma32(As[buf], Bs[buf], ty4, tx4, acc);
    }

#pragma unroll
    for (int p = 0; p < 2; p++)
#pragma unroll
        for (int j = 0; j < 4; j++) {
            float2 t = unpack2(acc[p][j]);
            int h = h0 + tx4 + j;
            int mm = m0 + ty4 + 2*p;
            int bb_ = mm >> 8, qq_ = mm & 255;
            g_w2[((size_t)(bb_*LL + qq_)*NHH + n)*HH + h] = t.x;
            int mm2 = mm + 1;
            int bb2 = mm2 >> 8, qq2 = mm2 & 255;
            g_w2[((size_t)(bb2*LL + qq2)*NHH + n)*HH + h] = t.y;
        }
}

// ---------------- A_C GEMM: g_ac[bn,q,k] = (qt+u) @ kt^T, grid (4,4,16) ----------------
__global__ __launch_bounds__(256, 2) void ac_kernel(const float* __restrict__ u_bias)
{
    int bn = blockIdx.z;
    int q0 = blockIdx.y * 64, k0 = blockIdx.x * 64;
    int n = bn & 7;

    __shared__ __align__(16) float As[2][32][68];
    __shared__ __align__(16) float Bs[2][32][68];

    int tid = threadIdx.x;
    int lrow = tid >> 2, lk = (tid & 3) * 8;
    int ty4 = (tid >> 4) * 4, tx4 = (tid & 15) * 4;

    const float* Arow = g_qt + ((size_t)bn*LL + q0 + lrow)*DHH + lk;
    const float* Brow = g_kt + ((size_t)bn*LL + k0 + lrow)*DHH + lk;
    const float* Urow = u_bias + n*DHH + lk;

    float4 ra0 = *(const float4*)(Arow),  ra1 = *(const float4*)(Arow + 4);
    float4 u0  = *(const float4*)(Urow),  u1  = *(const float4*)(Urow + 4);
    ra0.x += u0.x; ra0.y += u0.y; ra0.z += u0.z; ra0.w += u0.w;
    ra1.x += u1.x; ra1.y += u1.y; ra1.z += u1.z; ra1.w += u1.w;
    float4 rb0 = *(const float4*)(Brow),  rb1 = *(const float4*)(Brow + 4);

    u64 acc[2][4];
#pragma unroll
    for (int p = 0; p < 2; p++)
#pragma unroll
        for (int j = 0; j < 4; j++) acc[p][j] = 0ull;

#pragma unroll 1
    for (int s = 0; s < 2; s++) {
        int buf = s & 1;
        STS8A(buf, ra0, ra1); STS8B(buf, rb0, rb1);
        __syncthreads();
        if (s == 0) {
            ra0 = *(const float4*)(Arow + 32); ra1 = *(const float4*)(Arow + 36);
            float4 w0 = *(const float4*)(Urow + 32), w1 = *(const float4*)(Urow + 36);
            ra0.x += w0.x; ra0.y += w0.y; ra0.z += w0.z; ra0.w += w0.w;
            ra1.x += w1.x; ra1.y += w1.y; ra1.z += w1.z; ra1.w += w1.w;
            rb0 = *(const float4*)(Brow + 32); rb1 = *(const float4*)(Brow + 36);
        }
        mma32(As[buf], Bs[buf], ty4, tx4, acc);
    }

#pragma unroll
    for (int p = 0; p < 2; p++) {
        float2 t0 = unpack2(acc[p][0]), t1 = unpack2(acc[p][1]);
        float2 t2 = unpack2(acc[p][2]), t3 = unpack2(acc[p][3]);
        int q = q0 + ty4 + 2*p;
        *(float4*)&g_ac[((size_t)bn*LL + q)  *LL + k0 + tx4] = make_float4(t0.x, t1.x, t2.x, t3.x);
        *(float4*)&g_ac[((size_t)bn*LL + q+1)*LL + k0 + tx4] = make_float4(t0.y, t1.y, t2.y, t3.y);
    }
}

// ---------------- B_D + softmax: 256 thr, w2 in regs, 2-row ILP, 8-slot ring ----------------
// dyn smem: 8 warps * 8 slots * 512 floats = 128KB
__global__ __launch_bounds__(256, 1) void bd_kernel(
    const float* __restrict__ rel,
    const int* __restrict__ seq_len, const int* __restrict__ lex_num)
{
    extern __shared__ __align__(16) float ring[];
    __shared__ __align__(16) float ss[NHH * 260];   // scores, pitch 260

    int q = blockIdx.x, b = blockIdx.y;
    int tid = threadIdx.x, w = tid >> 5, lane = tid & 31;

    // preload A_C: warp w owns head w
    {
        const float* acp = g_ac + ((size_t)(b*NHH + w)*LL + q)*LL;
        *(float4*)&ss[w*260 + lane*8]     = *(const float4*)&acp[lane*8];
        *(float4*)&ss[w*260 + lane*8 + 4] = *(const float4*)&acp[lane*8 + 4];
    }

    // w2 into registers (lane owns h = j*128 + lane*4 .. +3, all 8 heads)
    const float* w2p = g_w2 + (size_t)(b*LL + q)*NHH*HH;
    ulonglong2 w2u[4][8];
#pragma unroll
    for (int j = 0; j < 4; j++)
#pragma unroll
        for (int n = 0; n < 8; n++)
            w2u[j][n] = *(const ulonglong2*)&w2p[n*HH + j*128 + lane*4];

    const float* relrow = rel + (((size_t)(b*LL + q))*LL + w*32)*HH + lane*4;
    float* myring = ring + w*8*HH;
    uint32_t rbase = (uint32_t)__cvta_generic_to_shared(myring) + lane*16;

#define ISSUE_ROW(row, slot) { const float* s_ = relrow + (size_t)(row)*HH; uint32_t d_ = rbase + (slot)*2048; \
    CP_ASYNC16(d_,      s_);       CP_ASYNC16(d_+512,  s_+128); \
    CP_ASYNC16(d_+1024, s_+256);   CP_ASYNC16(d_+1536, s_+384); }

    // prologue: 3 pairs (rows 0..5, slots 0..5)
    ISSUE_ROW(0, 0); ISSUE_ROW(1, 1); CP_COMMIT();
    ISSUE_ROW(2, 2); ISSUE_ROW(3, 3); CP_COMMIT();
    ISSUE_ROW(4, 4); ISSUE_ROW(5, 5); CP_COMMIT();
    __syncthreads();   // A_C preload visible

#pragma unroll 1
    for (int i = 0; i < 16; i++) {
        CP_WAIT2();    // current pair (oldest group) arrived
        int r0 = 2*i;
        const float* slotA = myring + ((r0    ) & 7)*HH;
        const float* slotB = myring + ((r0 + 1) & 7)*HH;

        ulonglong2 ra[4], rb[4];
#pragma unroll
        for (int j = 0; j < 4; j++) {
            ra[j] = *(const ulonglong2*)&slotA[j*128 + lane*4];
            rb[j] = *(const ulonglong2*)&slotB[j*128 + lane*4];
        }

        // issue next pair (rows r0+6, r0+7) into slots (r0+6)&7, (r0+7)&7
        if (i + 3 < 16) {
            ISSUE_ROW(r0 + 6, (r0 + 6) & 7);
            ISSUE_ROW(r0 + 7, (r0 + 7) & 7);
        }
        CP_COMMIT();   // commit (possibly empty) to keep group accounting fixed

        u64 pa[8], pb[8];
#pragma unroll
        for (int n = 0; n < 8; n++) { pa[n] = 0ull; pb[n] = 0ull; }
#pragma unroll
        for (int j = 0; j < 4; j++) {
#pragma unroll
            for (int n = 0; n < 8; n++) {
                pa[n] = fma2(w2u[j][n].x, ra[j].x, pa[n]);
                pa[n] = fma2(w2u[j][n].y, ra[j].y, pa[n]);
                pb[n] = fma2(w2u[j][n].x, rb[j].x, pb[n]);
                pb[n] = fma2(w2u[j][n].y, rb[j].y, pb[n]);
            }
        }

        // interleaved dual butterfly: head n lands on lanes 4n..4n+3
        bool h16 = (lane & 16) != 0;
        float aA[4], aB[4];
#pragma unroll
        for (int t = 0; t < 4; t++) {
            float2 tlA = unpack2(pa[t]), thA = unpack2(pa[t+4]);
            float slA = tlA.x + tlA.y, shA = thA.x + thA.y;
            float keepA = h16 ? shA : slA, sendA = h16 ? slA : shA;
            aA[t] = keepA + __shfl_xor_sync(0xffffffffu, sendA, 16);
            float2 tlB = unpack2(pb[t]), thB = unpack2(pb[t+4]);
            float slB = tlB.x + tlB.y, shB = thB.x + thB.y;
            float keepB = h16 ? shB : slB, sendB = h16 ? slB : shB;
            aB[t] = keepB + __shfl_xor_sync(0xffffffffu, sendB, 16);
        }
        bool h8 = (lane & 8) != 0;
        float cA[2], cB[2];
#pragma unroll
        for (int t = 0; t < 2; t++) {
            float keepA = h8 ? aA[t+2] : aA[t], sendA = h8 ? aA[t] : aA[t+2];
            cA[t] = keepA + __shfl_xor_sync(0xffffffffu, sendA, 8);
            float keepB = h8 ? aB[t+2] : aB[t], sendB = h8 ? aB[t] : aB[t+2];
            cB[t] = keepB + __shfl_xor_sync(0xffffffffu, sendB, 8);
        }
        bool h4 = (lane & 4) != 0;
        float keepA = h4 ? cA[1] : cA[0], sendA = h4 ? cA[0] : cA[1];
        float eA = keepA + __shfl_xor_sync(0xffffffffu, sendA, 4);
        float keepB = h4 ? cB[1] : cB[0], sendB = h4 ? cB[0] : cB[1];
        float eB = keepB + __shfl_xor_sync(0xffffffffu, sendB, 4);
        eA += __shfl_xor_sync(0xffffffffu, eA, 2);
        eB += __shfl_xor_sync(0xffffffffu, eB, 2);
        eA += __shfl_xor_sync(0xffffffffu, eA, 1);
        eB += __shfl_xor_sync(0xffffffffu, eB, 1);
        if ((lane & 3) == 0) {
            int base = (lane >> 2)*260 + w*32 + r0;
            ss[base]     += eA;
            ss[base + 1] += eB;
        }
    }
    __syncthreads();

    // softmax head w + write attn
    int total = seq_len[b] + lex_num[b];
    {
        float v[8];
        float4 s0 = *(const float4*)&ss[w*260 + lane*8];
        float4 s1 = *(const float4*)&ss[w*260 + lane*8 + 4];
        v[0]=s0.x; v[1]=s0.y; v[2]=s0.z; v[3]=s0.w;
        v[4]=s1.x; v[5]=s1.y; v[6]=s1.z; v[7]=s1.w;
#pragma unroll
        for (int t = 0; t < 8; t++) {
            int kidx = lane*8 + t;
            v[t] = (kidx < total) ? v[t] * 0.125f : -1e15f;
        }
        float mx = v[0];
#pragma unroll
        for (int t = 1; t < 8; t++) mx = fmaxf(mx, v[t]);
#pragma unroll
        for (int sft = 16; sft > 0; sft >>= 1) mx = fmaxf(mx, __shfl_xor_sync(0xffffffffu, mx, sft));
        float sum = 0.f;
#pragma unroll
        for (int t = 0; t < 8; t++) { v[t] = expf(v[t] - mx); sum += v[t]; }
#pragma unroll
        for (int sft = 16; sft > 0; sft >>= 1) sum += __shfl_xor_sync(0xffffffffu, sum, sft);
        float inv = 1.0f / sum;
#pragma unroll
        for (int t = 0; t < 8; t++) v[t] *= inv;
        float* op = g_attn + ((size_t)(b*NHH + w)*LL + q)*LL + lane*8;
        *(float4*)(op)     = make_float4(v[0], v[1], v[2], v[3]);
        *(float4*)(op + 4) = make_float4(v[4], v[5], v[6], v[7]);
    }
}

// ---------------- AV GEMM (NN): g_pre = attn @ v, grid (4,16) ----------------
__global__ __launch_bounds__(256, 2) void av_kernel()
{
    int q0 = blockIdx.x * 64, bn = blockIdx.y;
    int b = bn >> 3, n = bn & 7;

    __shared__ __align__(16) float As[2][32][68];
    __shared__ __align__(16) float Bs[2][32][68];

    int tid = threadIdx.x;
    int lrow = tid >> 2, lk = (tid & 3) * 8;
    int brow = tid >> 3, bcol = (tid & 7) * 8;
    int ty4 = (tid >> 4) * 4, tx4 = (tid & 15) * 4;

    const float* Arow = g_attn + ((size_t)bn*LL + q0 + lrow)*LL + lk;
    const float* Brow = g_vt   + (size_t)bn*LL*DHH + brow*DHH + bcol;

    float4 ra0 = *(const float4*)(Arow),  ra1 = *(const float4*)(Arow + 4);
    float4 rb0 = *(const float4*)(Brow),  rb1 = *(const float4*)(Brow + 4);

    u64 acc[2][4];
#pragma unroll
    for (int p = 0; p < 2; p++)
#pragma unroll
        for (int j = 0; j < 4; j++) acc[p][j] = 0ull;

#pragma unroll 1
    for (int s = 0; s < 8; s++) {
        int buf = s & 1;
        STS8A(buf, ra0, ra1);
        *(float4*)&Bs[buf][brow][bcol]     = rb0;
        *(float4*)&Bs[buf][brow][bcol + 4] = rb1;
        __syncthreads();
        if (s + 1 < 8) {
            ra0 = *(const float4*)(Arow + (s+1)*32);            ra1 = *(const float4*)(Arow + (s+1)*32 + 4);
            rb0 = *(const float4*)(Brow + (s+1)*32*DHH);        rb1 = *(const float4*)(Brow + (s+1)*32*DHH + 4);
        }
        mma32(As[buf], Bs[buf], ty4, tx4, acc);
    }

#pragma unroll
    for (int p = 0; p < 2; p++)
#pragma unroll
        for (int j = 0; j < 4; j++) {
            float2 t = unpack2(acc[p][j]);
            int d = tx4 + j;
            int q = q0 + ty4 + 2*p;
            g_pre[((size_t)(b*LL + q))    *HH + n*DHH + d] = t.x;
            g_pre[((size_t)(b*LL + q + 1))*HH + n*DHH + d] = t.y;
        }
}

// ---------------- final NT GEMM: out = g_pre @ Wf^T + bf, grid (8,8) ----------------
__global__ __launch_bounds__(256, 2) void wf_kernel(const float* __restrict__ Wf,
                                                    const float* __restrict__ bf,
                                                    float* __restrict__ out)
{
    __shared__ __align__(16) float As[2][32][68];
    __shared__ __align__(16) float Bs[2][32][68];

    int tid = threadIdx.x;
    int m0 = blockIdx.y * 64, n0 = blockIdx.x * 64;
    int lrow = tid >> 2, lk = (tid & 3) * 8;
    int ty4 = (tid >> 4) * 4, tx4 = (tid & 15) * 4;

    const float* Arow = g_pre + (m0 + lrow)*HH + lk;
    const float* Brow = Wf    + (n0 + lrow)*HH + lk;
    float4 ra0 = *(const float4*)(Arow),  ra1 = *(const float4*)(Arow + 4);
    float4 rb0 = *(const float4*)(Brow),  rb1 = *(const float4*)(Brow + 4);

    u64 acc[2][4];
#pragma unroll
    for (int p = 0; p < 2; p++)
#pragma unroll
        for (int j = 0; j < 4; j++) acc[p][j] = 0ull;

#pragma unroll 1
    for (int s = 0; s < 16; s++) {
        int buf = s & 1;
        STS8A(buf, ra0, ra1); STS8B(buf, rb0, rb1);
        __syncthreads();
        if (s + 1 < 16) {
            ra0 = *(const float4*)(Arow + (s+1)*32);  ra1 = *(const float4*)(Arow + (s+1)*32 + 4);
            rb0 = *(const float4*)(Brow + (s+1)*32);  rb1 = *(const float4*)(Brow + (s+1)*32 + 4);
        }
        mma32(As[buf], Bs[buf], ty4, tx4, acc);
    }

#pragma unroll
    for (int p = 0; p < 2; p++)
#pragma unroll
        for (int j = 0; j < 4; j++) {
            float2 t = unpack2(acc[p][j]);
            int c = n0 + tx4 + j;
            float bb = bf[c];
            int m = m0 + ty4 + 2*p;
            out[(size_t)m*HH + c]     = t.x + bb;
            out[(size_t)(m+1)*HH + c] = t.y + bb;
        }
}

// ---------------- launch ----------------
extern "C" void kernel_launch(void* const* d_in, const int* in_sizes, int n_in,
                              void* d_out, int out_size) {
    (void)in_sizes; (void)n_in; (void)out_size;
    const float* key     = (const float*)d_in[0];
    const float* query   = (const float*)d_in[1];
    const float* value   = (const float*)d_in[2];
    const float* rel     = (const float*)d_in[3];
    const float* Wk      = (const float*)d_in[4];
    const float* bk      = (const float*)d_in[5];
    const float* Wq      = (const float*)d_in[6];
    const float* bq      = (const float*)d_in[7];
    const float* Wv      = (const float*)d_in[8];
    const float* bv      = (const float*)d_in[9];
    const float* Wr      = (const float*)d_in[10];
    // d_in[11] = br: constant per score row -> cancels in softmax
    const float* u_bias  = (const float*)d_in[12];
    const float* v_bias  = (const float*)d_in[13];
    const float* Wf      = (const float*)d_in[14];
    const float* bf      = (const float*)d_in[15];
    const int*   seq_len = (const int*)d_in[16];
    const int*   lex_num = (const int*)d_in[17];
    float* out = (float*)d_out;

    static int bd_smem_set = 0;
    if (!bd_smem_set) {
        cudaFuncSetAttribute(bd_kernel, cudaFuncAttributeMaxDynamicSharedMemorySize, 131072);
        bd_smem_set = 1;
    }

    qkv_kernel<<<dim3(8, 8, 3), 256>>>(query, key, value, Wq, bq, Wk, bk, Wv, bv);
    w2_kernel<<<dim3(8, 8, NHH), 256>>>(Wr, v_bias);
    ac_kernel<<<dim3(4, 4, 16), 256>>>(u_bias);
    bd_kernel<<<dim3(LL, BB), 256, 131072>>>(rel, seq_len, lex_num);
    av_kernel<<<dim3(4, 16), 256>>>();
    wf_kernel<<<dim3(8, 8), 256>>>(Wf, bf, out);
}